// round 12
// baseline (speedup 1.0000x reference)
#include <cuda_runtime.h>

// DeformationPerturbationLayer == bilinear sampling of the image at
// src = pixel + w[b] * bulge_displacement(pixel).
//
// The reference materializes a dense [B,N,N] tent-weight matrix and does an
// einsum; relu(1-|offset|) is the bilinear hat function, so it collapses to
// 4-tap bilinear sampling — 4096x fewer MACs.
//
// Algebraic fact: src = x + w*(center-x)*g with w in [0,1), g in (0,1] is a
// convex combination of x and the image center => src in [0,63] always.
// The reference's zero-padding boundary handling is provably dead code;
// only the min(+1, 63) upper clamp survives (tap weight there is exactly 0).
//
// image: [C=3, H=64, W=64] fp32
// w:     [B=8, 1] fp32
// out:   [B=8, C=3, H=64, W=64] fp32
//
// FINAL CHAMPION (R11 config, best measured kernel dur 4.32us):
// grid 128 x 256, one thread per (b,pixel), 3 channels/thread, 12
// independent gathers (MLP=12) issued ahead of the weight math, and the
// dependent prefix to the first LDG minimized — log2(e)/512 folded into
// one constant K so the Gaussian is a single FMA + MUFU.EX2.
//
// Session evidence (11 rounds): kernel is launch-ramp + L2-round-trip
// bound (all pipes <1%, DRAM 0.1-0.2%, issue ~7%); wall = kernel +
// ~2.1us fixed graph-replay overhead, noise band 6.5-6.9us. Every other
// lever (3x work/thread, 2x instruction count, 4x occupancy, 4 grid
// shapes, float4 stores) was tested and falsified or regressed.

#define B_ 8
#define C_ 3
#define H_ 64
#define W_ 64
#define NPIX (H_ * W_)

__global__ __launch_bounds__(256, 8)
void deform_kernel(const float* __restrict__ w,
                   const float* __restrict__ img,
                   float* __restrict__ out)
{
    int idx = blockIdx.x * blockDim.x + threadIdx.x;   // 0 .. 32767, grid exact

    int b   = idx >> 12;          // / 4096
    int pix = idx & (NPIX - 1);   // % 4096
    int y   = pix >> 6;
    int x   = pix & 63;

    float wb = __ldg(w + b);      // broadcast load, issued first

    const float cx = (W_ - 1) * 0.5f;   // 31.5
    const float cy = (H_ - 1) * 0.5f;
    float fxp = __int2float_rn(x);
    float fyp = __int2float_rn(y);
    float dxc = cx - fxp;
    float dyc = cy - fyp;

    // exp(-(dxc^2+dyc^2)/512) == exp2(K*(dxc^2+dyc^2)), K = -log2(e)/512
    const float K = -1.44269504088896340736f / 512.0f;
    float e  = fmaf(dxc * K, dxc, (dyc * K) * dyc);    // 2 indep FMUL + 1 FMA
    float g  = exp2f(e);                               // MUFU.EX2 directly
    float wg = wb * g;

    float sx = fmaf(wg, dxc, fxp);     // in [0, 63] by convexity
    float sy = fmaf(wg, dyc, fyp);

    int x0 = __float2int_rd(sx);       // in [0, 63]
    int y0 = __float2int_rd(sy);
    float tx = sx - __int2float_rn(x0);
    float ty = sy - __int2float_rn(y0);

    int x1 = min(x0 + 1, W_ - 1);      // differs from x0+1 only when tx == 0
    int y1 = min(y0 + 1, H_ - 1);

    int r0 = y0 << 6;
    int r1 = y1 << 6;
    int i00 = r0 + x0;
    int i01 = r0 + x1;
    int i10 = r1 + x0;
    int i11 = r1 + x1;

    // all 12 gathers are independent — issue before the weight math
    float v00a = __ldg(img + i00);
    float v01a = __ldg(img + i01);
    float v10a = __ldg(img + i10);
    float v11a = __ldg(img + i11);
    float v00b = __ldg(img + NPIX + i00);
    float v01b = __ldg(img + NPIX + i01);
    float v10b = __ldg(img + NPIX + i10);
    float v11b = __ldg(img + NPIX + i11);
    float v00c = __ldg(img + 2 * NPIX + i00);
    float v01c = __ldg(img + 2 * NPIX + i01);
    float v10c = __ldg(img + 2 * NPIX + i10);
    float v11c = __ldg(img + 2 * NPIX + i11);

    float w11 = ty * tx;
    float w10 = ty - w11;              // ty * (1 - tx)
    float w01 = tx - w11;              // (1 - ty) * tx
    float w00 = 1.0f - ty - w01;       // (1 - ty) * (1 - tx)

    float* ob = out + b * (C_ * NPIX) + pix;
    ob[0]        = fmaf(w00, v00a, w01 * v01a) + fmaf(w10, v10a, w11 * v11a);
    ob[NPIX]     = fmaf(w00, v00b, w01 * v01b) + fmaf(w10, v10b, w11 * v11b);
    ob[2 * NPIX] = fmaf(w00, v00c, w01 * v01c) + fmaf(w10, v10c, w11 * v11c);
}

extern "C" void kernel_launch(void* const* d_in, const int* in_sizes, int n_in,
                              void* d_out, int out_size)
{
    const float* w   = (const float*)d_in[0];   // [8,1]
    const float* img = (const float*)d_in[1];   // [3,64,64]
    float* out = (float*)d_out;                 // [8,3,64,64]

    deform_kernel<<<(B_ * NPIX) / 256, 256>>>(w, img, out);
}

// round 13
// speedup vs baseline: 1.0386x; 1.0386x over previous
#include <cuda_runtime.h>

// DeformationPerturbationLayer == bilinear sampling of the image at
// src = pixel + w[b] * bulge_displacement(pixel).
//
// The reference materializes a dense [B,N,N] tent-weight matrix and does an
// einsum; relu(1-|offset|) is the bilinear hat function, so it collapses to
// 4-tap bilinear sampling — 4096x fewer MACs.
//
// Algebraic fact: src = x + w*(center-x)*g with w in [0,1), g in (0,1] is a
// convex combination of x and the image center => src in [0,63] always.
// The reference's zero-padding boundary handling is provably dead code;
// only the min(+1, 63) upper clamp survives (tap weight there is exactly 0).
//
// image: [C=3, H=64, W=64] fp32
// w:     [B=8, 1] fp32
// out:   [B=8, C=3, H=64, W=64] fp32
//
// FINAL CHAMPION — optimization complete at the measured hardware floor.
// grid 128 x 256, one thread per (b,pixel), 3 channels/thread, 12
// independent gathers (MLP=12) issued ahead of the weight math; dependent
// prefix to the first LDG minimized (log2(e)/512 folded into constant K,
// Gaussian = 1 FMA + MUFU.EX2). regs=29, single graph node.
//
// Session evidence (12 rounds): kernel dur 4.3-4.8us and wall 6.5-6.9us
// are pure run-to-run noise around a fixed floor = launch ramp (~5000 cyc)
// + one L2 round-trip per warp + ~2.1us graph-replay overhead. All pipes
// <1%, DRAM 0.1%. Falsified levers: work/thread (3x), instruction count
// (2x), occupancy (4x), grid shape (x4), float4 stores (regressed).

#define B_ 8
#define C_ 3
#define H_ 64
#define W_ 64
#define NPIX (H_ * W_)

__global__ __launch_bounds__(256, 8)
void deform_kernel(const float* __restrict__ w,
                   const float* __restrict__ img,
                   float* __restrict__ out)
{
    int idx = blockIdx.x * blockDim.x + threadIdx.x;   // 0 .. 32767, grid exact

    int b   = idx >> 12;          // / 4096
    int pix = idx & (NPIX - 1);   // % 4096
    int y   = pix >> 6;
    int x   = pix & 63;

    float wb = __ldg(w + b);      // broadcast load, issued first

    const float cx = (W_ - 1) * 0.5f;   // 31.5
    const float cy = (H_ - 1) * 0.5f;
    float fxp = __int2float_rn(x);
    float fyp = __int2float_rn(y);
    float dxc = cx - fxp;
    float dyc = cy - fyp;

    // exp(-(dxc^2+dyc^2)/512) == exp2(K*(dxc^2+dyc^2)), K = -log2(e)/512
    const float K = -1.44269504088896340736f / 512.0f;
    float e  = fmaf(dxc * K, dxc, (dyc * K) * dyc);    // 2 indep FMUL + 1 FMA
    float g  = exp2f(e);                               // MUFU.EX2 directly
    float wg = wb * g;

    float sx = fmaf(wg, dxc, fxp);     // in [0, 63] by convexity
    float sy = fmaf(wg, dyc, fyp);

    int x0 = __float2int_rd(sx);       // in [0, 63]
    int y0 = __float2int_rd(sy);
    float tx = sx - __int2float_rn(x0);
    float ty = sy - __int2float_rn(y0);

    int x1 = min(x0 + 1, W_ - 1);      // differs from x0+1 only when tx == 0
    int y1 = min(y0 + 1, H_ - 1);

    int r0 = y0 << 6;
    int r1 = y1 << 6;
    int i00 = r0 + x0;
    int i01 = r0 + x1;
    int i10 = r1 + x0;
    int i11 = r1 + x1;

    // all 12 gathers are independent — issue before the weight math
    float v00a = __ldg(img + i00);
    float v01a = __ldg(img + i01);
    float v10a = __ldg(img + i10);
    float v11a = __ldg(img + i11);
    float v00b = __ldg(img + NPIX + i00);
    float v01b = __ldg(img + NPIX + i01);
    float v10b = __ldg(img + NPIX + i10);
    float v11b = __ldg(img + NPIX + i11);
    float v00c = __ldg(img + 2 * NPIX + i00);
    float v01c = __ldg(img + 2 * NPIX + i01);
    float v10c = __ldg(img + 2 * NPIX + i10);
    float v11c = __ldg(img + 2 * NPIX + i11);

    float w11 = ty * tx;
    float w10 = ty - w11;              // ty * (1 - tx)
    float w01 = tx - w11;              // (1 - ty) * tx
    float w00 = 1.0f - ty - w01;       // (1 - ty) * (1 - tx)

    float* ob = out + b * (C_ * NPIX) + pix;
    ob[0]        = fmaf(w00, v00a, w01 * v01a) + fmaf(w10, v10a, w11 * v11a);
    ob[NPIX]     = fmaf(w00, v00b, w01 * v01b) + fmaf(w10, v10b, w11 * v11b);
    ob[2 * NPIX] = fmaf(w00, v00c, w01 * v01c) + fmaf(w10, v10c, w11 * v11c);
}

extern "C" void kernel_launch(void* const* d_in, const int* in_sizes, int n_in,
                              void* d_out, int out_size)
{
    const float* w   = (const float*)d_in[0];   // [8,1]
    const float* img = (const float*)d_in[1];   // [3,64,64]
    float* out = (float*)d_out;                 // [8,3,64,64]

    deform_kernel<<<(B_ * NPIX) / 256, 256>>>(w, img, out);
}